// round 6
// baseline (speedup 1.0000x reference)
#include <cuda_runtime.h>

#define TT       64
#define NN       2048
#define RPB      16                 // rows (post-neurons) per CTA
#define NCTA     (NN / RPB)         // 128 CTAs (1 per SM)
#define NTHREADS 1024
#define NWARPS   32                 // warp pair (2c,2c+1) owns colblock c (128 cols)
#define FULLM    0xffffffffu

// per-CTA flag: (step_count << 16) | 16-bit spike mask. Count monotonic (48b)
// across graph replays; every launch adds exactly TT-1 per CTA.
__device__ unsigned long long g_flag[NCTA];

__device__ __forceinline__ unsigned long long ldv64(const unsigned long long* a) {
    unsigned long long r;
    asm volatile("ld.volatile.global.u64 %0, [%1];" : "=l"(r) : "l"(a) : "memory");
    return r;
}
__device__ __forceinline__ void stv64(unsigned long long* a, unsigned long long v) {
    asm volatile("st.volatile.global.u64 [%0], %1;" :: "l"(a), "l"(v) : "memory");
}

__global__ void __launch_bounds__(NTHREADS, 1)
snn_persistent(const float* __restrict__ exc,
               const float* __restrict__ w_in,
               const float* __restrict__ tpre_in,
               const float* __restrict__ tpost_in,
               float* __restrict__ out)
{
    __shared__ float    w_s[RPB * NN];        // 128 KB, rows x cols
    __shared__ unsigned zb[2][NCTA];          // spike masks, double buffered
    __shared__ float    part[16 * RPB];       // [colblock][row]

    const int tid  = threadIdx.x;
    const int warp = tid >> 5;
    const int lane = tid & 31;
    const int bid  = blockIdx.x;
    const int rowBase = bid * RPB;

    const int cb      = warp >> 1;                 // colblock 0..15
    const int rowHalf = (warp & 1) * 8;            // rows 0-7 or 8-15
    const int colBase = cb * 128 + lane * 4;       // this thread's 4 global cols
    const int colWord = colBase >> 4;              // CTA mask covering those cols
    const int colSh   = colBase & 15;

    const unsigned long long base = g_flag[bid] >> 16;   // launch-uniform

    // ---- prologue: own 16 rows of w -> smem (only big DRAM read) ----
    {
        const float4* src = reinterpret_cast<const float4*>(w_in + (size_t)rowBase * NN);
        float4*       dst = reinterpret_cast<float4*>(w_s);
        #pragma unroll
        for (int k = 0; k < RPB * NN / 4 / NTHREADS; ++k)
            dst[tid + k * NTHREADS] = src[tid + k * NTHREADS];
    }
    // register traces: tp for own 4 cols (warp pair replicates - deterministic);
    // tpo replica for this warp's 8 rows in lanes 0..7
    float4 p = *reinterpret_cast<const float4*>(tpre_in + colBase);
    float  q = (lane < 8) ? tpost_in[rowBase + rowHalf + lane] : 0.0f;
    float  v = 0.0f;                               // membrane (warp0 lanes<16)
    __syncthreads();

    // ---- step 0: z = 0 -> i_syn = 0, no weight update ----
    if (warp == 0) {
        float zn = 0.0f;
        if (lane < RPB) {
            const float x = __ldcg(&exc[rowBase + lane]);
            v = __fadd_rn(v, __fmul_rn(0.1f, __fadd_rn(__fadd_rn(-v, 0.0f), x)));
            zn = (__fsub_rn(v, 1.0f) > 0.0f) ? 1.0f : 0.0f;
            v = (zn > 0.0f) ? 0.0f : v;
            out[rowBase + lane] = zn;
        }
        const unsigned bits = __ballot_sync(FULLM, zn > 0.0f) & 0xffffu;
        if (lane == 0)
            stv64(&g_flag[bid], ((base + 1ull) << 16) | (unsigned long long)bits);
    }

    for (int i = 1; i < TT; ++i) {
        const int buf = i & 1;

        // prefetch own input current (warp0; overlaps the poll)
        float x = 0.0f;
        if (warp == 0 && lane < RPB) x = __ldcg(&exc[i * NN + rowBase + lane]);

        // ---- poller warp 1: wait for all 128 CTAs' step-(i-1) flags ----
        if (warp == 1) {
            const unsigned long long tgt = base + (unsigned long long)i;
            unsigned long long f0, f1, f2, f3;
            do {
                f0 = ldv64(&g_flag[lane]);
                f1 = ldv64(&g_flag[lane + 32]);
                f2 = ldv64(&g_flag[lane + 64]);
                f3 = ldv64(&g_flag[lane + 96]);
            } while (__ballot_sync(FULLM,
                        ((f0 >> 16) >= tgt) & ((f1 >> 16) >= tgt) &
                        ((f2 >> 16) >= tgt) & ((f3 >> 16) >= tgt)) != FULLM);
            zb[buf][lane]      = (unsigned)(f0 & 0xffffu);
            zb[buf][lane + 32] = (unsigned)(f1 & 0xffffu);
            zb[buf][lane + 64] = (unsigned)(f2 & 0xffffu);
            zb[buf][lane + 96] = (unsigned)(f3 & 0xffffu);
        }
        asm volatile("bar.sync 2, %0;" :: "n"(NTHREADS) : "memory");  // z_{i-1} ready

        // ---- expand z bits ----
        const unsigned cw = zb[buf][colWord];
        const unsigned zw = zb[buf][bid];
        const bool  c0 = (cw >> (colSh + 0)) & 1u;
        const bool  c1 = (cw >> (colSh + 1)) & 1u;
        const bool  c2 = (cw >> (colSh + 2)) & 1u;
        const bool  c3 = (cw >> (colSh + 3)) & 1u;
        const float z0 = c0 ? 1.0f : 0.0f;
        const float z1 = c1 ? 1.0f : 0.0f;
        const float z2 = c2 ? 1.0f : 0.0f;
        const float z3 = c3 ? 1.0f : 0.0f;
        const float zo = ((zw >> (rowHalf + (lane & 7))) & 1u) ? 1.0f : 0.0f;

        // ---- trace updates (exact reference rounding) ----
        p.x = __fadd_rn(p.x, __fmul_rn(0.05f, __fadd_rn(-p.x, z0)));
        p.y = __fadd_rn(p.y, __fmul_rn(0.05f, __fadd_rn(-p.y, z1)));
        p.z = __fadd_rn(p.z, __fmul_rn(0.05f, __fadd_rn(-p.z, z2)));
        p.w = __fadd_rn(p.w, __fmul_rn(0.05f, __fadd_rn(-p.w, z3)));
        q   = __fadd_rn(q,   __fmul_rn(0.05f, __fadd_rn(-q,   zo)));

        // sp = rn(1e-3 * tp) (== reference dw+ when z_row=1; selected by zr)
        const float spx = __fmul_rn(1e-3f, p.x);
        const float spy = __fmul_rn(1e-3f, p.y);
        const float spz = __fmul_rn(1e-3f, p.z);
        const float spw = __fmul_rn(1e-3f, p.w);
        const float bq  = __fmul_rn(1e-3f, q);
        float b[8];
        #pragma unroll
        for (int r = 0; r < 8; ++r) b[r] = __shfl_sync(FULLM, bq, r);

        // ---- fused pass over this warp's 8 rows: w += dw (clip), acc = w.z ----
        float acc[8];
        #pragma unroll
        for (int batch = 0; batch < 2; ++batch) {
            float4 wv[4];
            #pragma unroll
            for (int r = 0; r < 4; ++r)
                wv[r] = *reinterpret_cast<float4*>(
                    &w_s[(rowHalf + batch * 4 + r) * NN + colBase]);
            #pragma unroll
            for (int r = 0; r < 4; ++r) {
                const int R  = batch * 4 + r;          // local row 0..7
                const bool zr = (zw >> (rowHalf + R)) & 1u;
                float4 w4 = wv[r];
                float t1, t2, wn;
                t1 = zr ? spx : 0.0f;  t2 = c0 ? b[R] : 0.0f;
                wn = __fadd_rn(w4.x, __fsub_rn(t1, t2));
                w4.x = fmaxf(wn, 0.0f);                // upper clip provably dead
                t1 = zr ? spy : 0.0f;  t2 = c1 ? b[R] : 0.0f;
                wn = __fadd_rn(w4.y, __fsub_rn(t1, t2));
                w4.y = fmaxf(wn, 0.0f);
                t1 = zr ? spz : 0.0f;  t2 = c2 ? b[R] : 0.0f;
                wn = __fadd_rn(w4.z, __fsub_rn(t1, t2));
                w4.z = fmaxf(wn, 0.0f);
                t1 = zr ? spw : 0.0f;  t2 = c3 ? b[R] : 0.0f;
                wn = __fadd_rn(w4.w, __fsub_rn(t1, t2));
                w4.w = fmaxf(wn, 0.0f);
                *reinterpret_cast<float4*>(
                    &w_s[(rowHalf + R) * NN + colBase]) = w4;

                float d = w4.x * z0;
                d = fmaf(w4.y, z1, d);
                d = fmaf(w4.z, z2, d);
                d = fmaf(w4.w, z3, d);
                acc[R] = d;
            }
        }

        // ---- tree reduction: 8 accs x 32 lanes -> 8 row sums ----
        // xor-stride order 16,8,4,2,1 (identical summation tree to prior rounds)
        #pragma unroll
        for (int r = 0; r < 4; ++r) {
            float keep = (lane & 16) ? acc[r + 4] : acc[r];
            float send = (lane & 16) ? acc[r]     : acc[r + 4];
            acc[r] = keep + __shfl_xor_sync(FULLM, send, 16);
        }
        #pragma unroll
        for (int r = 0; r < 2; ++r) {
            float keep = (lane & 8) ? acc[r + 2] : acc[r];
            float send = (lane & 8) ? acc[r]     : acc[r + 2];
            acc[r] = keep + __shfl_xor_sync(FULLM, send, 8);
        }
        {
            float keep = (lane & 4) ? acc[1] : acc[0];
            float send = (lane & 4) ? acc[0] : acc[1];
            acc[0] = keep + __shfl_xor_sync(FULLM, send, 4);
        }
        acc[0] += __shfl_xor_sync(FULLM, acc[0], 2);
        acc[0] += __shfl_xor_sync(FULLM, acc[0], 1);
        const int r_own = ((lane >> 4) & 1) * 4 + ((lane >> 3) & 1) * 2 + ((lane >> 2) & 1);
        if ((lane & 3) == 0)
            part[cb * RPB + rowHalf + r_own] = acc[0];

        // ---- hand part[] to warp0; other warps roll ahead ----
        if (warp == 0) {
            asm volatile("bar.sync 1, %0;" :: "n"(NTHREADS) : "memory");
            float zn = 0.0f;
            if (lane < RPB) {
                float isyn = 0.0f;
                #pragma unroll
                for (int k = 0; k < 16; ++k) isyn += part[k * RPB + lane];
                v = __fadd_rn(v, __fmul_rn(0.1f, __fadd_rn(__fadd_rn(-v, isyn), x)));
                zn = (__fsub_rn(v, 1.0f) > 0.0f) ? 1.0f : 0.0f;
                v = (zn > 0.0f) ? 0.0f : v;
                out[(size_t)i * NN + rowBase + lane] = zn;
            }
            if (i < TT - 1) {
                const unsigned bits = __ballot_sync(FULLM, zn > 0.0f) & 0xffffu;
                if (lane == 0)
                    stv64(&g_flag[bid],
                          ((base + (unsigned long long)(i + 1)) << 16) |
                          (unsigned long long)bits);
            }
        } else {
            asm volatile("bar.arrive 1, %0;" :: "n"(NTHREADS) : "memory");
        }
    }
}

extern "C" void kernel_launch(void* const* d_in, const int* in_sizes, int n_in,
                              void* d_out, int out_size) {
    const float* exc   = (const float*)d_in[0];  // [T, N]
    const float* w     = (const float*)d_in[1];  // [N, N]
    const float* tpre  = (const float*)d_in[2];  // [N]
    const float* tpost = (const float*)d_in[3];  // [N]
    float*       out   = (float*)d_out;          // [T, N]

    snn_persistent<<<NCTA, NTHREADS>>>(exc, w, tpre, tpost, out);
}

// round 7
// speedup vs baseline: 1.3693x; 1.3693x over previous
#include <cuda_runtime.h>

#define TT       64
#define NN       2048
#define RPB      16                 // rows (post-neurons) per CTA
#define NCTA     (NN / RPB)         // 128 CTAs (1 per SM)
#define NTHREADS 512
#define NWARPS   16                 // warp w owns columns [w*128, w*128+128)
#define FULLM    0xffffffffu
#define FSTRIDE  4                  // flag padding: 4 u64 = 32B sector per CTA

// per-CTA flag: (step_count << 16) | 16-bit spike mask; 32B-padded so no two
// CTAs share an L2 sector. Count monotonic (48b) across graph replays.
__device__ unsigned long long g_flag[NCTA * FSTRIDE];

__device__ __forceinline__ unsigned long long ldv64(const unsigned long long* a) {
    unsigned long long r;
    asm volatile("ld.volatile.global.u64 %0, [%1];" : "=l"(r) : "l"(a) : "memory");
    return r;
}
__device__ __forceinline__ void stv64(unsigned long long* a, unsigned long long v) {
    asm volatile("st.volatile.global.u64 [%0], %1;" :: "l"(a), "l"(v) : "memory");
}

__global__ void __launch_bounds__(NTHREADS, 1)
snn_persistent(const float* __restrict__ exc,
               const float* __restrict__ w_in,
               const float* __restrict__ tpre_in,
               const float* __restrict__ tpost_in,
               float* __restrict__ out)
{
    __shared__ float    w_s[RPB * NN];        // 128 KB, rows x cols
    __shared__ unsigned zb[2][NCTA];          // spike masks, double buffered
    __shared__ float    part[NWARPS * RPB];   // [srcWarp][row]

    const int tid  = threadIdx.x;
    const int warp = tid >> 5;
    const int lane = tid & 31;
    const int bid  = blockIdx.x;
    const int rowBase = bid * RPB;
    const int colBase = warp * 128 + lane * 4;     // this thread's 4 global cols
    const int colWord = colBase >> 4;              // CTA mask covering those cols
    const int colSh   = colBase & 15;

    const unsigned long long base = g_flag[bid * FSTRIDE] >> 16;   // launch-uniform

    // ---- prologue: own 16 rows of w -> smem (only big DRAM read) ----
    {
        const float4* src = reinterpret_cast<const float4*>(w_in + (size_t)rowBase * NN);
        float4*       dst = reinterpret_cast<float4*>(w_s);
        #pragma unroll
        for (int k = 0; k < RPB * NN / 4 / NTHREADS; ++k)
            dst[tid + k * NTHREADS] = src[tid + k * NTHREADS];
    }
    // register traces: tp for own 4 cols; tpo replica for own 16 rows (lanes<16)
    float4 p = *reinterpret_cast<const float4*>(tpre_in + colBase);
    float  q = (lane < RPB) ? tpost_in[rowBase + lane] : 0.0f;
    float  v = 0.0f;                               // membrane (warp0 lanes<16)
    __syncthreads();

    // ---- step 0: z = 0 -> i_syn = 0, no weight update ----
    if (warp == 0) {
        float zn = 0.0f;
        if (lane < RPB) {
            const float x = __ldcg(&exc[rowBase + lane]);
            v = __fadd_rn(v, __fmul_rn(0.1f, __fadd_rn(__fadd_rn(-v, 0.0f), x)));
            zn = (__fsub_rn(v, 1.0f) > 0.0f) ? 1.0f : 0.0f;
            v = (zn > 0.0f) ? 0.0f : v;
            out[rowBase + lane] = zn;
        }
        const unsigned bits = __ballot_sync(FULLM, zn > 0.0f) & 0xffffu;
        if (lane == 0)
            stv64(&g_flag[bid * FSTRIDE],
                  ((base + 1ull) << 16) | (unsigned long long)bits);
    }

    for (int i = 1; i < TT; ++i) {
        const int buf = i & 1;

        // prefetch own input current (warp0; overlaps the poll)
        float x = 0.0f;
        if (warp == 0 && lane < RPB) x = __ldcg(&exc[i * NN + rowBase + lane]);

        // ---- poller warp 1: wait for all 128 CTAs' step-(i-1) flags ----
        if (warp == 1) {
            const unsigned long long tgt = base + (unsigned long long)i;
            unsigned long long f0, f1, f2, f3;
            do {
                f0 = ldv64(&g_flag[(lane      ) * FSTRIDE]);
                f1 = ldv64(&g_flag[(lane + 32 ) * FSTRIDE]);
                f2 = ldv64(&g_flag[(lane + 64 ) * FSTRIDE]);
                f3 = ldv64(&g_flag[(lane + 96 ) * FSTRIDE]);
            } while (__ballot_sync(FULLM,
                        ((f0 >> 16) >= tgt) & ((f1 >> 16) >= tgt) &
                        ((f2 >> 16) >= tgt) & ((f3 >> 16) >= tgt)) != FULLM);
            zb[buf][lane]      = (unsigned)(f0 & 0xffffu);
            zb[buf][lane + 32] = (unsigned)(f1 & 0xffffu);
            zb[buf][lane + 64] = (unsigned)(f2 & 0xffffu);
            zb[buf][lane + 96] = (unsigned)(f3 & 0xffffu);
        }
        asm volatile("bar.sync 2, %0;" :: "n"(NTHREADS) : "memory");  // z_{i-1} ready

        // ---- expand z bits ----
        const unsigned cw = zb[buf][colWord];
        const unsigned zw = zb[buf][bid];
        const float z0 = ((cw >> (colSh + 0)) & 1u) ? 1.0f : 0.0f;
        const float z1 = ((cw >> (colSh + 1)) & 1u) ? 1.0f : 0.0f;
        const float z2 = ((cw >> (colSh + 2)) & 1u) ? 1.0f : 0.0f;
        const float z3 = ((cw >> (colSh + 3)) & 1u) ? 1.0f : 0.0f;
        const float zo = (lane < RPB) ? (((zw >> lane) & 1u) ? 1.0f : 0.0f) : 0.0f;

        // ---- trace updates (exact reference rounding) ----
        p.x = __fadd_rn(p.x, __fmul_rn(0.05f, __fadd_rn(-p.x, z0)));
        p.y = __fadd_rn(p.y, __fmul_rn(0.05f, __fadd_rn(-p.y, z1)));
        p.z = __fadd_rn(p.z, __fmul_rn(0.05f, __fadd_rn(-p.z, z2)));
        p.w = __fadd_rn(p.w, __fmul_rn(0.05f, __fadd_rn(-p.w, z3)));
        q   = __fadd_rn(q,   __fmul_rn(0.05f, __fadd_rn(-q,   zo)));

        // sp = rn(1e-3 * tp); b_i = rn(1e-3 * tpo_i)
        const float spx = __fmul_rn(1e-3f, p.x);
        const float spy = __fmul_rn(1e-3f, p.y);
        const float spz = __fmul_rn(1e-3f, p.z);
        const float spw = __fmul_rn(1e-3f, p.w);
        const float bq  = __fmul_rn(1e-3f, q);
        float b[RPB];
        #pragma unroll
        for (int r = 0; r < RPB; ++r) b[r] = __shfl_sync(FULLM, bq, r);

        // ---- fused pass: w += dw (clip), acc_r = w_new . z ----
        // dw rounding chain (z in {0,1} makes products exact):
        //   t1 = zr ? sp_j : 0                        (exact)
        //   d  = fma(-b_i, z_j, t1) = rn(t1 - t2)     (reference rounding)
        //   wn = rn(w + d); clip lower (upper provably dead)
        float acc[RPB];
        #pragma unroll
        for (int half = 0; half < 2; ++half) {
            float4 wv[8];
            #pragma unroll
            for (int r = 0; r < 8; ++r)
                wv[r] = *reinterpret_cast<float4*>(&w_s[(half * 8 + r) * NN + colBase]);
            #pragma unroll
            for (int r = 0; r < 8; ++r) {
                const int  R  = half * 8 + r;
                const bool zr = (zw >> R) & 1u;
                const float nb = -b[R];
                float4 w4 = wv[r];

                float t1, d;
                t1 = zr ? spx : 0.0f;
                d  = __fmaf_rn(nb, z0, t1);
                w4.x = fmaxf(__fadd_rn(w4.x, d), 0.0f);
                t1 = zr ? spy : 0.0f;
                d  = __fmaf_rn(nb, z1, t1);
                w4.y = fmaxf(__fadd_rn(w4.y, d), 0.0f);
                t1 = zr ? spz : 0.0f;
                d  = __fmaf_rn(nb, z2, t1);
                w4.z = fmaxf(__fadd_rn(w4.z, d), 0.0f);
                t1 = zr ? spw : 0.0f;
                d  = __fmaf_rn(nb, z3, t1);
                w4.w = fmaxf(__fadd_rn(w4.w, d), 0.0f);

                *reinterpret_cast<float4*>(&w_s[R * NN + colBase]) = w4;

                float s = w4.x * z0;
                s = fmaf(w4.y, z1, s);
                s = fmaf(w4.z, z2, s);
                s = fmaf(w4.w, z3, s);
                acc[R] = s;
            }
        }

        // ---- multi-value tree reduction (identical order to all passing rounds) ----
        #pragma unroll
        for (int r = 0; r < 8; ++r) {
            float keep = (lane & 16) ? acc[r + 8] : acc[r];
            float send = (lane & 16) ? acc[r]     : acc[r + 8];
            acc[r] = keep + __shfl_xor_sync(FULLM, send, 16);
        }
        #pragma unroll
        for (int r = 0; r < 4; ++r) {
            float keep = (lane & 8) ? acc[r + 4] : acc[r];
            float send = (lane & 8) ? acc[r]     : acc[r + 4];
            acc[r] = keep + __shfl_xor_sync(FULLM, send, 8);
        }
        #pragma unroll
        for (int r = 0; r < 2; ++r) {
            float keep = (lane & 4) ? acc[r + 2] : acc[r];
            float send = (lane & 4) ? acc[r]     : acc[r + 2];
            acc[r] = keep + __shfl_xor_sync(FULLM, send, 4);
        }
        {
            float keep = (lane & 2) ? acc[1] : acc[0];
            float send = (lane & 2) ? acc[0] : acc[1];
            acc[0] = keep + __shfl_xor_sync(FULLM, send, 2);
        }
        acc[0] += __shfl_xor_sync(FULLM, acc[0], 1);
        if ((lane & 1) == 0) part[warp * RPB + (lane >> 1)] = acc[0];

        // ---- hand part[] to warp0; warps 1-15 roll ahead ----
        if (warp == 0) {
            asm volatile("bar.sync 1, %0;" :: "n"(NTHREADS) : "memory");
            float zn = 0.0f;
            if (lane < RPB) {
                float isyn = 0.0f;
                #pragma unroll
                for (int k = 0; k < NWARPS; ++k) isyn += part[k * RPB + lane];
                v = __fadd_rn(v, __fmul_rn(0.1f, __fadd_rn(__fadd_rn(-v, isyn), x)));
                zn = (__fsub_rn(v, 1.0f) > 0.0f) ? 1.0f : 0.0f;
                v = (zn > 0.0f) ? 0.0f : v;
                out[(size_t)i * NN + rowBase + lane] = zn;
            }
            if (i < TT - 1) {
                const unsigned bits = __ballot_sync(FULLM, zn > 0.0f) & 0xffffu;
                if (lane == 0)
                    stv64(&g_flag[bid * FSTRIDE],
                          ((base + (unsigned long long)(i + 1)) << 16) |
                          (unsigned long long)bits);
            }
        } else {
            asm volatile("bar.arrive 1, %0;" :: "n"(NTHREADS) : "memory");
        }
    }
}

extern "C" void kernel_launch(void* const* d_in, const int* in_sizes, int n_in,
                              void* d_out, int out_size) {
    const float* exc   = (const float*)d_in[0];  // [T, N]
    const float* w     = (const float*)d_in[1];  // [N, N]
    const float* tpre  = (const float*)d_in[2];  // [N]
    const float* tpost = (const float*)d_in[3];  // [N]
    float*       out   = (float*)d_out;          // [T, N]

    snn_persistent<<<NCTA, NTHREADS>>>(exc, w, tpre, tpost, out);
}

// round 10
// speedup vs baseline: 1.5406x; 1.1251x over previous
#include <cuda_runtime.h>

#define TT       64
#define NN       2048
#define RPB      16                 // rows (post-neurons) per CTA
#define NCTA     (NN / RPB)         // 128 CTAs (1 per SM)
#define NTHREADS 512
#define NWARPS   16                 // warp w owns columns [w*128, w*128+128)
#define FULLM    0xffffffffu
#define FSTRIDE  4                  // flag padding: 4 u64 = 32B sector per CTA

// per-CTA flag: (step_count << 16) | 16-bit spike mask; 32B-padded.
// Count monotonic (48b) across graph replays.
__device__ unsigned long long g_flag[NCTA * FSTRIDE];

__device__ __forceinline__ unsigned long long ldv64(const unsigned long long* a) {
    unsigned long long r;
    asm volatile("ld.volatile.global.u64 %0, [%1];" : "=l"(r) : "l"(a) : "memory");
    return r;
}
__device__ __forceinline__ void stv64(unsigned long long* a, unsigned long long v) {
    asm volatile("st.volatile.global.u64 [%0], %1;" :: "l"(a), "l"(v) : "memory");
}

__global__ void __launch_bounds__(NTHREADS, 1)
snn_persistent(const float* __restrict__ exc,
               const float* __restrict__ w_in,
               const float* __restrict__ tpre_in,
               const float* __restrict__ tpost_in,
               float* __restrict__ out)
{
    __shared__ unsigned zb[2][NCTA];          // spike masks, double buffered
    __shared__ float    part[NWARPS * RPB];   // [srcWarp][row]

    const int tid  = threadIdx.x;
    const int warp = tid >> 5;
    const int lane = tid & 31;
    const int bid  = blockIdx.x;
    const int rowBase = bid * RPB;
    const int colBase = warp * 128 + lane * 4;     // this thread's 4 global cols
    const int colWord = colBase >> 4;              // CTA mask covering those cols
    const int colSh   = colBase & 15;

    const unsigned long long base = g_flag[bid * FSTRIDE] >> 16;   // launch-uniform

    // ---- prologue: own 16 rows of w -> REGISTERS (no smem w at all) ----
    float w[RPB][4];
    #pragma unroll
    for (int r = 0; r < RPB; ++r) {
        const float4 t = *reinterpret_cast<const float4*>(
            w_in + (size_t)(rowBase + r) * NN + colBase);
        w[r][0] = t.x; w[r][1] = t.y; w[r][2] = t.z; w[r][3] = t.w;
    }
    // register traces: tp for own 4 cols; tpo replica for own 16 rows (lanes<16)
    float4 p = *reinterpret_cast<const float4*>(tpre_in + colBase);
    float  q = (lane < RPB) ? tpost_in[rowBase + lane] : 0.0f;
    float  v = 0.0f;                               // membrane (warp0 lanes<16)

    // all threads have read `base` before warp0 overwrites the flag below
    __syncthreads();

    // ---- step 0: z = 0 -> i_syn = 0, no weight update ----
    if (warp == 0) {
        float zn = 0.0f;
        if (lane < RPB) {
            const float x = __ldcg(&exc[rowBase + lane]);
            v = __fadd_rn(v, __fmul_rn(0.1f, __fadd_rn(__fadd_rn(-v, 0.0f), x)));
            zn = (__fsub_rn(v, 1.0f) > 0.0f) ? 1.0f : 0.0f;
            v = (zn > 0.0f) ? 0.0f : v;
            out[rowBase + lane] = zn;
        }
        const unsigned bits = __ballot_sync(FULLM, zn > 0.0f) & 0xffffu;
        if (lane == 0)
            stv64(&g_flag[bid * FSTRIDE],
                  ((base + 1ull) << 16) | (unsigned long long)bits);
    }

    for (int i = 1; i < TT; ++i) {
        const int buf = i & 1;

        // prefetch own input current (warp0; overlaps the poll)
        float x = 0.0f;
        if (warp == 0 && lane < RPB) x = __ldcg(&exc[i * NN + rowBase + lane]);

        // ---- poller warp 1: wait for all 128 CTAs' step-(i-1) flags ----
        if (warp == 1) {
            const unsigned long long tgt = base + (unsigned long long)i;
            unsigned long long f0, f1, f2, f3;
            do {
                f0 = ldv64(&g_flag[(lane      ) * FSTRIDE]);
                f1 = ldv64(&g_flag[(lane + 32 ) * FSTRIDE]);
                f2 = ldv64(&g_flag[(lane + 64 ) * FSTRIDE]);
                f3 = ldv64(&g_flag[(lane + 96 ) * FSTRIDE]);
            } while (__ballot_sync(FULLM,
                        ((f0 >> 16) >= tgt) & ((f1 >> 16) >= tgt) &
                        ((f2 >> 16) >= tgt) & ((f3 >> 16) >= tgt)) != FULLM);
            zb[buf][lane]      = (unsigned)(f0 & 0xffffu);
            zb[buf][lane + 32] = (unsigned)(f1 & 0xffffu);
            zb[buf][lane + 64] = (unsigned)(f2 & 0xffffu);
            zb[buf][lane + 96] = (unsigned)(f3 & 0xffffu);
        }
        asm volatile("bar.sync 2, %0;" :: "n"(NTHREADS) : "memory");  // z_{i-1} ready

        // ---- expand z bits ----
        const unsigned cw = zb[buf][colWord];
        const unsigned zw = zb[buf][bid];
        const float z0 = ((cw >> (colSh + 0)) & 1u) ? 1.0f : 0.0f;
        const float z1 = ((cw >> (colSh + 1)) & 1u) ? 1.0f : 0.0f;
        const float z2 = ((cw >> (colSh + 2)) & 1u) ? 1.0f : 0.0f;
        const float z3 = ((cw >> (colSh + 3)) & 1u) ? 1.0f : 0.0f;
        const float zo = (lane < RPB) ? (((zw >> lane) & 1u) ? 1.0f : 0.0f) : 0.0f;

        // ---- trace updates (exact reference rounding) ----
        p.x = __fadd_rn(p.x, __fmul_rn(0.05f, __fadd_rn(-p.x, z0)));
        p.y = __fadd_rn(p.y, __fmul_rn(0.05f, __fadd_rn(-p.y, z1)));
        p.z = __fadd_rn(p.z, __fmul_rn(0.05f, __fadd_rn(-p.z, z2)));
        p.w = __fadd_rn(p.w, __fmul_rn(0.05f, __fadd_rn(-p.w, z3)));
        q   = __fadd_rn(q,   __fmul_rn(0.05f, __fadd_rn(-q,   zo)));

        // sp = rn(1e-3 * tp); b_i = rn(1e-3 * tpo_i) broadcast per row
        const float spx = __fmul_rn(1e-3f, p.x);
        const float spy = __fmul_rn(1e-3f, p.y);
        const float spz = __fmul_rn(1e-3f, p.z);
        const float spw = __fmul_rn(1e-3f, p.w);
        const float bq  = __fmul_rn(1e-3f, q);

        // ---- fused pass in registers, rows in two batches of 8 ----
        // per element: t1 = zr ? sp_j : 0 (exact); d = fma(-b, z_j, t1) = rn(t1-t2);
        // w = max(rn(w+d), 0)  [upper clip provably dead]; acc += w*z_j (fmaf chain)
        float acc[8];

        #pragma unroll
        for (int r = 0; r < 8; ++r) {
            const float br = __shfl_sync(FULLM, bq, r);
            const float nb = -br;
            const bool  zr = (zw >> r) & 1u;
            float t1, d;
            t1 = zr ? spx : 0.0f;  d = __fmaf_rn(nb, z0, t1);
            w[r][0] = fmaxf(__fadd_rn(w[r][0], d), 0.0f);
            t1 = zr ? spy : 0.0f;  d = __fmaf_rn(nb, z1, t1);
            w[r][1] = fmaxf(__fadd_rn(w[r][1], d), 0.0f);
            t1 = zr ? spz : 0.0f;  d = __fmaf_rn(nb, z2, t1);
            w[r][2] = fmaxf(__fadd_rn(w[r][2], d), 0.0f);
            t1 = zr ? spw : 0.0f;  d = __fmaf_rn(nb, z3, t1);
            w[r][3] = fmaxf(__fadd_rn(w[r][3], d), 0.0f);

            float s = w[r][0] * z0;
            s = fmaf(w[r][1], z1, s);
            s = fmaf(w[r][2], z2, s);
            s = fmaf(w[r][3], z3, s);
            acc[r] = s;
        }
        // 8-value tree over 32 lanes (stride order 16,8,4,2,1 — verified mapping)
        #pragma unroll
        for (int r = 0; r < 4; ++r) {
            float keep = (lane & 16) ? acc[r + 4] : acc[r];
            float send = (lane & 16) ? acc[r]     : acc[r + 4];
            acc[r] = keep + __shfl_xor_sync(FULLM, send, 16);
        }
        #pragma unroll
        for (int r = 0; r < 2; ++r) {
            float keep = (lane & 8) ? acc[r + 2] : acc[r];
            float send = (lane & 8) ? acc[r]     : acc[r + 2];
            acc[r] = keep + __shfl_xor_sync(FULLM, send, 8);
        }
        {
            float keep = (lane & 4) ? acc[1] : acc[0];
            float send = (lane & 4) ? acc[0] : acc[1];
            acc[0] = keep + __shfl_xor_sync(FULLM, send, 4);
        }
        acc[0] += __shfl_xor_sync(FULLM, acc[0], 2);
        acc[0] += __shfl_xor_sync(FULLM, acc[0], 1);
        {
            const int r_own = ((lane >> 4) & 1) * 4 + ((lane >> 3) & 1) * 2
                            + ((lane >> 2) & 1);
            if ((lane & 3) == 0) part[warp * RPB + r_own] = acc[0];
        }

        #pragma unroll
        for (int r = 8; r < RPB; ++r) {
            const float br = __shfl_sync(FULLM, bq, r);
            const float nb = -br;
            const bool  zr = (zw >> r) & 1u;
            float t1, d;
            t1 = zr ? spx : 0.0f;  d = __fmaf_rn(nb, z0, t1);
            w[r][0] = fmaxf(__fadd_rn(w[r][0], d), 0.0f);
            t1 = zr ? spy : 0.0f;  d = __fmaf_rn(nb, z1, t1);
            w[r][1] = fmaxf(__fadd_rn(w[r][1], d), 0.0f);
            t1 = zr ? spz : 0.0f;  d = __fmaf_rn(nb, z2, t1);
            w[r][2] = fmaxf(__fadd_rn(w[r][2], d), 0.0f);
            t1 = zr ? spw : 0.0f;  d = __fmaf_rn(nb, z3, t1);
            w[r][3] = fmaxf(__fadd_rn(w[r][3], d), 0.0f);

            float s = w[r][0] * z0;
            s = fmaf(w[r][1], z1, s);
            s = fmaf(w[r][2], z2, s);
            s = fmaf(w[r][3], z3, s);
            acc[r - 8] = s;
        }
        #pragma unroll
        for (int r = 0; r < 4; ++r) {
            float keep = (lane & 16) ? acc[r + 4] : acc[r];
            float send = (lane & 16) ? acc[r]     : acc[r + 4];
            acc[r] = keep + __shfl_xor_sync(FULLM, send, 16);
        }
        #pragma unroll
        for (int r = 0; r < 2; ++r) {
            float keep = (lane & 8) ? acc[r + 2] : acc[r];
            float send = (lane & 8) ? acc[r]     : acc[r + 2];
            acc[r] = keep + __shfl_xor_sync(FULLM, send, 8);
        }
        {
            float keep = (lane & 4) ? acc[1] : acc[0];
            float send = (lane & 4) ? acc[0] : acc[1];
            acc[0] = keep + __shfl_xor_sync(FULLM, send, 4);
        }
        acc[0] += __shfl_xor_sync(FULLM, acc[0], 2);
        acc[0] += __shfl_xor_sync(FULLM, acc[0], 1);
        {
            const int r_own = ((lane >> 4) & 1) * 4 + ((lane >> 3) & 1) * 2
                            + ((lane >> 2) & 1);
            if ((lane & 3) == 0) part[warp * RPB + 8 + r_own] = acc[0];
        }

        // ---- hand part[] to warp0; warps 1-15 roll ahead ----
        if (warp == 0) {
            asm volatile("bar.sync 1, %0;" :: "n"(NTHREADS) : "memory");
            float zn = 0.0f;
            if (lane < RPB) {
                float isyn = 0.0f;
                #pragma unroll
                for (int k = 0; k < NWARPS; ++k) isyn += part[k * RPB + lane];
                v = __fadd_rn(v, __fmul_rn(0.1f, __fadd_rn(__fadd_rn(-v, isyn), x)));
                zn = (__fsub_rn(v, 1.0f) > 0.0f) ? 1.0f : 0.0f;
                v = (zn > 0.0f) ? 0.0f : v;
                out[(size_t)i * NN + rowBase + lane] = zn;
            }
            if (i < TT - 1) {
                const unsigned bits = __ballot_sync(FULLM, zn > 0.0f) & 0xffffu;
                if (lane == 0)
                    stv64(&g_flag[bid * FSTRIDE],
                          ((base + (unsigned long long)(i + 1)) << 16) |
                          (unsigned long long)bits);
            }
        } else {
            asm volatile("bar.arrive 1, %0;" :: "n"(NTHREADS) : "memory");
        }
    }
}

extern "C" void kernel_launch(void* const* d_in, const int* in_sizes, int n_in,
                              void* d_out, int out_size) {
    const float* exc   = (const float*)d_in[0];  // [T, N]
    const float* w     = (const float*)d_in[1];  // [N, N]
    const float* tpre  = (const float*)d_in[2];  // [N]
    const float* tpost = (const float*)d_in[3];  // [N]
    float*       out   = (float*)d_out;          // [T, N]

    snn_persistent<<<NCTA, NTHREADS>>>(exc, w, tpre, tpost, out);
}

// round 11
// speedup vs baseline: 1.5506x; 1.0065x over previous
#include <cuda_runtime.h>

#define TT       64
#define NN       2048
#define RPB      16                 // rows (post-neurons) per CTA
#define NCTA     (NN / RPB)         // 128 CTAs (1 per SM)
#define NTHREADS 1024
#define FULLM    0xffffffffu
#define FSTRIDE  4                  // flag padding: 4 u64 = 32B sector per CTA

// per-CTA flag: (step_count << 16) | 16-bit spike mask; 32B-padded.
// Count monotonic (48b) across graph replays.
__device__ unsigned long long g_flag[NCTA * FSTRIDE];

__device__ __forceinline__ unsigned long long ldv64(const unsigned long long* a) {
    unsigned long long r;
    asm volatile("ld.volatile.global.u64 %0, [%1];" : "=l"(r) : "l"(a) : "memory");
    return r;
}
__device__ __forceinline__ void stv64(unsigned long long* a, unsigned long long v) {
    asm volatile("st.volatile.global.u64 [%0], %1;" :: "l"(a), "l"(v) : "memory");
}

__global__ void __launch_bounds__(NTHREADS, 1)
snn_persistent(const float* __restrict__ exc,
               const float* __restrict__ w_in,
               const float* __restrict__ tpre_in,
               const float* __restrict__ tpost_in,
               float* __restrict__ out)
{
    __shared__ unsigned zb[2][NCTA];          // spike masks, double buffered
    __shared__ float    part[16 * RPB];       // [colblock][row]

    const int tid  = threadIdx.x;
    const int warp = tid >> 5;
    const int lane = tid & 31;
    const int bid  = blockIdx.x;
    const int rowBase = bid * RPB;

    const int cb      = warp >> 1;                 // colblock 0..15
    const int rowHalf = (warp & 1) * 8;            // rows 0-7 or 8-15 of this CTA
    const int colBase = cb * 128 + lane * 4;       // this thread's 4 global cols
    const int colWord = colBase >> 4;              // CTA mask covering those cols
    const int colSh   = colBase & 15;

    const unsigned long long base = g_flag[bid * FSTRIDE] >> 16;   // launch-uniform

    // ---- prologue: this warp's 8 rows of w -> REGISTERS ----
    float w[8][4];
    #pragma unroll
    for (int r = 0; r < 8; ++r) {
        const float4 t = *reinterpret_cast<const float4*>(
            w_in + (size_t)(rowBase + rowHalf + r) * NN + colBase);
        w[r][0] = t.x; w[r][1] = t.y; w[r][2] = t.z; w[r][3] = t.w;
    }
    // register traces: tp for own 4 cols (warp-pair replicates, deterministic);
    // tpo replica for this warp's 8 rows in lanes 0..7
    float4 p = *reinterpret_cast<const float4*>(tpre_in + colBase);
    float  q = (lane < 8) ? tpost_in[rowBase + rowHalf + lane] : 0.0f;
    float  v = 0.0f;                               // membrane (warp0 lanes<16)

    // all threads have read `base` before warp0 overwrites the flag below
    __syncthreads();

    // ---- step 0: z = 0 -> i_syn = 0, no weight update ----
    if (warp == 0) {
        float zn = 0.0f;
        if (lane < RPB) {
            const float x = __ldcg(&exc[rowBase + lane]);
            v = __fadd_rn(v, __fmul_rn(0.1f, __fadd_rn(__fadd_rn(-v, 0.0f), x)));
            zn = (__fsub_rn(v, 1.0f) > 0.0f) ? 1.0f : 0.0f;
            v = (zn > 0.0f) ? 0.0f : v;
            out[rowBase + lane] = zn;
        }
        const unsigned bits = __ballot_sync(FULLM, zn > 0.0f) & 0xffffu;
        if (lane == 0)
            stv64(&g_flag[bid * FSTRIDE],
                  ((base + 1ull) << 16) | (unsigned long long)bits);
    }

    for (int i = 1; i < TT; ++i) {
        const int buf = i & 1;

        // prefetch own input current (warp0; overlaps the poll)
        float x = 0.0f;
        if (warp == 0 && lane < RPB) x = __ldcg(&exc[i * NN + rowBase + lane]);

        // ---- poller warp 1: wait for all 128 CTAs' step-(i-1) flags ----
        if (warp == 1) {
            const unsigned long long tgt = base + (unsigned long long)i;
            unsigned long long f0, f1, f2, f3;
            do {
                f0 = ldv64(&g_flag[(lane      ) * FSTRIDE]);
                f1 = ldv64(&g_flag[(lane + 32 ) * FSTRIDE]);
                f2 = ldv64(&g_flag[(lane + 64 ) * FSTRIDE]);
                f3 = ldv64(&g_flag[(lane + 96 ) * FSTRIDE]);
            } while (__ballot_sync(FULLM,
                        ((f0 >> 16) >= tgt) & ((f1 >> 16) >= tgt) &
                        ((f2 >> 16) >= tgt) & ((f3 >> 16) >= tgt)) != FULLM);
            zb[buf][lane]      = (unsigned)(f0 & 0xffffu);
            zb[buf][lane + 32] = (unsigned)(f1 & 0xffffu);
            zb[buf][lane + 64] = (unsigned)(f2 & 0xffffu);
            zb[buf][lane + 96] = (unsigned)(f3 & 0xffffu);
        }
        asm volatile("bar.sync 2, %0;" :: "n"(NTHREADS) : "memory");  // z_{i-1} ready

        // ---- expand z bits ----
        const unsigned cw = zb[buf][colWord];
        const unsigned zw = zb[buf][bid];
        const float z0 = ((cw >> (colSh + 0)) & 1u) ? 1.0f : 0.0f;
        const float z1 = ((cw >> (colSh + 1)) & 1u) ? 1.0f : 0.0f;
        const float z2 = ((cw >> (colSh + 2)) & 1u) ? 1.0f : 0.0f;
        const float z3 = ((cw >> (colSh + 3)) & 1u) ? 1.0f : 0.0f;
        const float zo = (lane < 8)
            ? (((zw >> (rowHalf + lane)) & 1u) ? 1.0f : 0.0f) : 0.0f;

        // ---- trace updates (exact reference rounding) ----
        p.x = __fadd_rn(p.x, __fmul_rn(0.05f, __fadd_rn(-p.x, z0)));
        p.y = __fadd_rn(p.y, __fmul_rn(0.05f, __fadd_rn(-p.y, z1)));
        p.z = __fadd_rn(p.z, __fmul_rn(0.05f, __fadd_rn(-p.z, z2)));
        p.w = __fadd_rn(p.w, __fmul_rn(0.05f, __fadd_rn(-p.w, z3)));
        q   = __fadd_rn(q,   __fmul_rn(0.05f, __fadd_rn(-q,   zo)));

        // sp = rn(1e-3 * tp); b_i = rn(1e-3 * tpo_i) broadcast per row
        const float spx = __fmul_rn(1e-3f, p.x);
        const float spy = __fmul_rn(1e-3f, p.y);
        const float spz = __fmul_rn(1e-3f, p.z);
        const float spw = __fmul_rn(1e-3f, p.w);
        const float bq  = __fmul_rn(1e-3f, q);

        // ---- fused pass over this warp's 8 rows, in 2 batches of 4 ----
        // per element: t1 = zr ? sp_j : 0 (exact); d = fma(-b, z_j, t1) = rn(t1-t2);
        // w = max(rn(w+d), 0) [upper clip provably dead]; acc fmaf chain (fixed order)
        #pragma unroll
        for (int batch = 0; batch < 2; ++batch) {
            float acc[4];
            #pragma unroll
            for (int rr = 0; rr < 4; ++rr) {
                const int  r  = batch * 4 + rr;        // local row 0..7
                const float br = __shfl_sync(FULLM, bq, r);
                const float nb = -br;
                const bool  zr = (zw >> (rowHalf + r)) & 1u;
                float t1, d;
                t1 = zr ? spx : 0.0f;  d = __fmaf_rn(nb, z0, t1);
                w[r][0] = fmaxf(__fadd_rn(w[r][0], d), 0.0f);
                t1 = zr ? spy : 0.0f;  d = __fmaf_rn(nb, z1, t1);
                w[r][1] = fmaxf(__fadd_rn(w[r][1], d), 0.0f);
                t1 = zr ? spz : 0.0f;  d = __fmaf_rn(nb, z2, t1);
                w[r][2] = fmaxf(__fadd_rn(w[r][2], d), 0.0f);
                t1 = zr ? spw : 0.0f;  d = __fmaf_rn(nb, z3, t1);
                w[r][3] = fmaxf(__fadd_rn(w[r][3], d), 0.0f);

                float s = w[r][0] * z0;
                s = fmaf(w[r][1], z1, s);
                s = fmaf(w[r][2], z2, s);
                s = fmaf(w[r][3], z3, s);
                acc[rr] = s;
            }
            // 4-value xor tree over 32 lanes (per-row pairing order 16,8,4,2,1
            // -> bit-identical to the verified 8/16-value trees)
            #pragma unroll
            for (int r = 0; r < 2; ++r) {
                float keep = (lane & 16) ? acc[r + 2] : acc[r];
                float send = (lane & 16) ? acc[r]     : acc[r + 2];
                acc[r] = keep + __shfl_xor_sync(FULLM, send, 16);
            }
            {
                float keep = (lane & 8) ? acc[1] : acc[0];
                float send = (lane & 8) ? acc[0] : acc[1];
                acc[0] = keep + __shfl_xor_sync(FULLM, send, 8);
            }
            acc[0] += __shfl_xor_sync(FULLM, acc[0], 4);
            acc[0] += __shfl_xor_sync(FULLM, acc[0], 2);
            acc[0] += __shfl_xor_sync(FULLM, acc[0], 1);
            {
                const int r_own = ((lane >> 4) & 1) * 2 + ((lane >> 3) & 1);
                if ((lane & 7) == 0)
                    part[cb * RPB + rowHalf + batch * 4 + r_own] = acc[0];
            }
        }

        // ---- hand part[] to warp0; other warps roll ahead ----
        if (warp == 0) {
            asm volatile("bar.sync 1, %0;" :: "n"(NTHREADS) : "memory");
            float zn = 0.0f;
            if (lane < RPB) {
                float isyn = 0.0f;
                #pragma unroll
                for (int k = 0; k < 16; ++k) isyn += part[k * RPB + lane];
                v = __fadd_rn(v, __fmul_rn(0.1f, __fadd_rn(__fadd_rn(-v, isyn), x)));
                zn = (__fsub_rn(v, 1.0f) > 0.0f) ? 1.0f : 0.0f;
                v = (zn > 0.0f) ? 0.0f : v;
                out[(size_t)i * NN + rowBase + lane] = zn;
            }
            if (i < TT - 1) {
                const unsigned bits = __ballot_sync(FULLM, zn > 0.0f) & 0xffffu;
                if (lane == 0)
                    stv64(&g_flag[bid * FSTRIDE],
                          ((base + (unsigned long long)(i + 1)) << 16) |
                          (unsigned long long)bits);
            }
        } else {
            asm volatile("bar.arrive 1, %0;" :: "n"(NTHREADS) : "memory");
        }
    }
}

extern "C" void kernel_launch(void* const* d_in, const int* in_sizes, int n_in,
                              void* d_out, int out_size) {
    const float* exc   = (const float*)d_in[0];  // [T, N]
    const float* w     = (const float*)d_in[1];  // [N, N]
    const float* tpre  = (const float*)d_in[2];  // [N]
    const float* tpost = (const float*)d_in[3];  // [N]
    float*       out   = (float*)d_out;          // [T, N]

    snn_persistent<<<NCTA, NTHREADS>>>(exc, w, tpre, tpost, out);
}

// round 12
// speedup vs baseline: 1.5957x; 1.0291x over previous
#include <cuda_runtime.h>

#define TT       64
#define NN       2048
#define RPB      16                 // rows (post-neurons) per CTA
#define NCTA     (NN / RPB)         // 128 CTAs (1 per SM)
#define NTHREADS 1024
#define FULLM    0xffffffffu
#define FSTRIDE  4                  // flag padding: 4 u64 = 32B sector per CTA

// per-CTA flag: (step_count << 16) | 16-bit spike mask; 32B-padded.
// Count monotonic (48b) across graph replays.
__device__ unsigned long long g_flag[NCTA * FSTRIDE];

__device__ __forceinline__ unsigned long long ldv64(const unsigned long long* a) {
    unsigned long long r;
    asm volatile("ld.volatile.global.u64 %0, [%1];" : "=l"(r) : "l"(a) : "memory");
    return r;
}
__device__ __forceinline__ void stv64(unsigned long long* a, unsigned long long v) {
    asm volatile("st.volatile.global.u64 [%0], %1;" :: "l"(a), "l"(v) : "memory");
}

__global__ void __launch_bounds__(NTHREADS, 1)
snn_persistent(const float* __restrict__ exc,
               const float* __restrict__ w_in,
               const float* __restrict__ tpre_in,
               const float* __restrict__ tpost_in,
               float* __restrict__ out)
{
    __shared__ unsigned zb[2][NCTA];          // spike masks, double buffered
    __shared__ float    part[16 * RPB];       // [colblock][row]

    const int tid  = threadIdx.x;
    const int warp = tid >> 5;
    const int lane = tid & 31;
    const int bid  = blockIdx.x;
    const int rowBase = bid * RPB;

    const int cb      = warp >> 1;                 // colblock 0..15
    const int rowHalf = (warp & 1) * 8;            // rows 0-7 or 8-15 of this CTA
    const int colBase = cb * 128 + lane * 4;       // this thread's 4 global cols
    const int colWord = colBase >> 4;              // CTA mask covering those cols
    const int colSh   = colBase & 15;

    const unsigned long long base = g_flag[bid * FSTRIDE] >> 16;   // launch-uniform

    // ---- prologue: this warp's 8 rows of w -> REGISTERS ----
    float w[8][4];
    #pragma unroll
    for (int r = 0; r < 8; ++r) {
        const float4 t = *reinterpret_cast<const float4*>(
            w_in + (size_t)(rowBase + rowHalf + r) * NN + colBase);
        w[r][0] = t.x; w[r][1] = t.y; w[r][2] = t.z; w[r][3] = t.w;
    }
    // register traces: tp for own 4 cols (warp-pair replicates, deterministic);
    // tpo replica for this warp's 8 rows in lanes 0..7
    float4 p = *reinterpret_cast<const float4*>(tpre_in + colBase);
    float  q = (lane < 8) ? tpost_in[rowBase + rowHalf + lane] : 0.0f;
    float  v = 0.0f;                               // membrane (warp0 lanes<16)

    // all threads have read `base` before warp0 overwrites the flag below
    __syncthreads();

    // ---- step 0: z = 0 -> i_syn = 0, no weight update ----
    if (warp == 0) {
        float zn = 0.0f;
        if (lane < RPB) {
            const float x = __ldcg(&exc[rowBase + lane]);
            v = __fadd_rn(v, __fmul_rn(0.1f, __fadd_rn(__fadd_rn(-v, 0.0f), x)));
            zn = (__fsub_rn(v, 1.0f) > 0.0f) ? 1.0f : 0.0f;
            v = (zn > 0.0f) ? 0.0f : v;
            out[rowBase + lane] = zn;
        }
        const unsigned bits = __ballot_sync(FULLM, zn > 0.0f) & 0xffffu;
        if (lane == 0)
            stv64(&g_flag[bid * FSTRIDE],
                  ((base + 1ull) << 16) | (unsigned long long)bits);
    }

    for (int i = 1; i < TT; ++i) {
        const int buf = i & 1;

        // prefetch own input current (warp0; overlaps the poll)
        float x = 0.0f;
        if (warp == 0 && lane < RPB) x = __ldcg(&exc[i * NN + rowBase + lane]);

        // ---- poller warp 1: wait for all 128 CTAs' step-(i-1) flags ----
        if (warp == 1) {
            const unsigned long long tgt = base + (unsigned long long)i;
            unsigned long long f0, f1, f2, f3;
            do {
                f0 = ldv64(&g_flag[(lane      ) * FSTRIDE]);
                f1 = ldv64(&g_flag[(lane + 32 ) * FSTRIDE]);
                f2 = ldv64(&g_flag[(lane + 64 ) * FSTRIDE]);
                f3 = ldv64(&g_flag[(lane + 96 ) * FSTRIDE]);
            } while (__ballot_sync(FULLM,
                        ((f0 >> 16) >= tgt) & ((f1 >> 16) >= tgt) &
                        ((f2 >> 16) >= tgt) & ((f3 >> 16) >= tgt)) != FULLM);
            zb[buf][lane]      = (unsigned)(f0 & 0xffffu);
            zb[buf][lane + 32] = (unsigned)(f1 & 0xffffu);
            zb[buf][lane + 64] = (unsigned)(f2 & 0xffffu);
            zb[buf][lane + 96] = (unsigned)(f3 & 0xffffu);
        }
        asm volatile("bar.sync 2, %0;" :: "n"(NTHREADS) : "memory");  // z_{i-1} ready

        // ---- expand z bits ----
        const unsigned cw = zb[buf][colWord];
        const unsigned zw = zb[buf][bid];
        const float z0 = ((cw >> (colSh + 0)) & 1u) ? 1.0f : 0.0f;
        const float z1 = ((cw >> (colSh + 1)) & 1u) ? 1.0f : 0.0f;
        const float z2 = ((cw >> (colSh + 2)) & 1u) ? 1.0f : 0.0f;
        const float z3 = ((cw >> (colSh + 3)) & 1u) ? 1.0f : 0.0f;
        const float zo = (lane < 8)
            ? (((zw >> (rowHalf + lane)) & 1u) ? 1.0f : 0.0f) : 0.0f;

        // ---- trace updates (exact reference rounding) ----
        p.x = __fadd_rn(p.x, __fmul_rn(0.05f, __fadd_rn(-p.x, z0)));
        p.y = __fadd_rn(p.y, __fmul_rn(0.05f, __fadd_rn(-p.y, z1)));
        p.z = __fadd_rn(p.z, __fmul_rn(0.05f, __fadd_rn(-p.z, z2)));
        p.w = __fadd_rn(p.w, __fmul_rn(0.05f, __fadd_rn(-p.w, z3)));
        q   = __fadd_rn(q,   __fmul_rn(0.05f, __fadd_rn(-q,   zo)));

        // sp = rn(1e-3 * tp); b_i = rn(1e-3 * tpo_i), broadcasts front-loaded
        const float spx = __fmul_rn(1e-3f, p.x);
        const float spy = __fmul_rn(1e-3f, p.y);
        const float spz = __fmul_rn(1e-3f, p.z);
        const float spw = __fmul_rn(1e-3f, p.w);
        const float bq  = __fmul_rn(1e-3f, q);
        float nb[8];
        #pragma unroll
        for (int r = 0; r < 8; ++r) nb[r] = -__shfl_sync(FULLM, bq, r);

        // ---- fused pass over this warp's 8 rows (single batch, max ILP) ----
        // per element: t1 = zr ? sp_j : 0 (exact); d = fma(-b, z_j, t1) = rn(t1-t2);
        // w = max(rn(w+d), 0) [upper clip provably dead]; acc fmaf chain (fixed order)
        float acc[8];
        #pragma unroll
        for (int r = 0; r < 8; ++r) {
            const bool zr = (zw >> (rowHalf + r)) & 1u;
            float t1, d;
            t1 = zr ? spx : 0.0f;  d = __fmaf_rn(nb[r], z0, t1);
            w[r][0] = fmaxf(__fadd_rn(w[r][0], d), 0.0f);
            t1 = zr ? spy : 0.0f;  d = __fmaf_rn(nb[r], z1, t1);
            w[r][1] = fmaxf(__fadd_rn(w[r][1], d), 0.0f);
            t1 = zr ? spz : 0.0f;  d = __fmaf_rn(nb[r], z2, t1);
            w[r][2] = fmaxf(__fadd_rn(w[r][2], d), 0.0f);
            t1 = zr ? spw : 0.0f;  d = __fmaf_rn(nb[r], z3, t1);
            w[r][3] = fmaxf(__fadd_rn(w[r][3], d), 0.0f);

            float s = w[r][0] * z0;
            s = fmaf(w[r][1], z1, s);
            s = fmaf(w[r][2], z2, s);
            s = fmaf(w[r][3], z3, s);
            acc[r] = s;
        }

        // ---- 8-value xor tree over 32 lanes (R8-verified mapping) ----
        #pragma unroll
        for (int r = 0; r < 4; ++r) {
            float keep = (lane & 16) ? acc[r + 4] : acc[r];
            float send = (lane & 16) ? acc[r]     : acc[r + 4];
            acc[r] = keep + __shfl_xor_sync(FULLM, send, 16);
        }
        #pragma unroll
        for (int r = 0; r < 2; ++r) {
            float keep = (lane & 8) ? acc[r + 2] : acc[r];
            float send = (lane & 8) ? acc[r]     : acc[r + 2];
            acc[r] = keep + __shfl_xor_sync(FULLM, send, 8);
        }
        {
            float keep = (lane & 4) ? acc[1] : acc[0];
            float send = (lane & 4) ? acc[0] : acc[1];
            acc[0] = keep + __shfl_xor_sync(FULLM, send, 4);
        }
        acc[0] += __shfl_xor_sync(FULLM, acc[0], 2);
        acc[0] += __shfl_xor_sync(FULLM, acc[0], 1);
        {
            const int r_own = ((lane >> 4) & 1) * 4 + ((lane >> 3) & 1) * 2
                            + ((lane >> 2) & 1);
            if ((lane & 3) == 0)
                part[cb * RPB + rowHalf + r_own] = acc[0];
        }

        // ---- hand part[] to warp0; other warps roll ahead ----
        if (warp == 0) {
            asm volatile("bar.sync 1, %0;" :: "n"(NTHREADS) : "memory");
            float zn = 0.0f;
            if (lane < RPB) {
                float isyn = 0.0f;
                #pragma unroll
                for (int k = 0; k < 16; ++k) isyn += part[k * RPB + lane];
                v = __fadd_rn(v, __fmul_rn(0.1f, __fadd_rn(__fadd_rn(-v, isyn), x)));
                zn = (__fsub_rn(v, 1.0f) > 0.0f) ? 1.0f : 0.0f;
                v = (zn > 0.0f) ? 0.0f : v;
                out[(size_t)i * NN + rowBase + lane] = zn;
            }
            if (i < TT - 1) {
                const unsigned bits = __ballot_sync(FULLM, zn > 0.0f) & 0xffffu;
                if (lane == 0)
                    stv64(&g_flag[bid * FSTRIDE],
                          ((base + (unsigned long long)(i + 1)) << 16) |
                          (unsigned long long)bits);
            }
        } else {
            asm volatile("bar.arrive 1, %0;" :: "n"(NTHREADS) : "memory");
        }
    }
}

extern "C" void kernel_launch(void* const* d_in, const int* in_sizes, int n_in,
                              void* d_out, int out_size) {
    const float* exc   = (const float*)d_in[0];  // [T, N]
    const float* w     = (const float*)d_in[1];  // [N, N]
    const float* tpre  = (const float*)d_in[2];  // [N]
    const float* tpost = (const float*)d_in[3];  // [N]
    float*       out   = (float*)d_out;          // [T, N]

    snn_persistent<<<NCTA, NTHREADS>>>(exc, w, tpre, tpost, out);
}

// round 14
// speedup vs baseline: 1.6233x; 1.0173x over previous
#include <cuda_runtime.h>

#define TT       64
#define NN       2048
#define RPB      16                 // rows (post-neurons) per CTA
#define NCTA     (NN / RPB)         // 128 CTAs (1 per SM)
#define NTHREADS 1024
#define FULLM    0xffffffffu
#define FSTRIDE  4                  // flag padding: 4 u64 = 32B sector per CTA
#define W_UPD    31                 // updater warp (highest wid -> arbiter priority)
#define W_POLL   30                 // poller warp

// per-CTA flag: (step_count << 16) | 16-bit spike mask; 32B-padded.
// Count monotonic (48b) across graph replays.
__device__ unsigned long long g_flag[NCTA * FSTRIDE];

__device__ __forceinline__ unsigned long long ldv64(const unsigned long long* a) {
    unsigned long long r;
    asm volatile("ld.volatile.global.u64 %0, [%1];" : "=l"(r) : "l"(a) : "memory");
    return r;
}
__device__ __forceinline__ void stv64(unsigned long long* a, unsigned long long v) {
    asm volatile("st.volatile.global.u64 [%0], %1;" :: "l"(a), "l"(v) : "memory");
}

__global__ void __launch_bounds__(NTHREADS, 1)
snn_persistent(const float* __restrict__ exc,
               const float* __restrict__ w_in,
               const float* __restrict__ tpre_in,
               const float* __restrict__ tpost_in,
               float* __restrict__ out)
{
    __shared__ unsigned zb[2][NCTA];          // spike masks, double buffered
    __shared__ float    part[16 * RPB];       // [colblock][row]

    const int tid  = threadIdx.x;
    const int warp = tid >> 5;
    const int lane = tid & 31;
    const int bid  = blockIdx.x;
    const int rowBase = bid * RPB;

    const int cb      = warp >> 1;                 // colblock 0..15
    const int rowHalf = (warp & 1) * 8;            // rows 0-7 or 8-15 of this CTA
    const int colBase = cb * 128 + lane * 4;       // this thread's 4 global cols
    const int colWord = colBase >> 4;              // CTA mask covering those cols
    const int colSh   = colBase & 15;

    const unsigned long long base = g_flag[bid * FSTRIDE] >> 16;   // launch-uniform

    // ---- prologue: this warp's 8 rows of w -> REGISTERS ----
    float w[8][4];
    #pragma unroll
    for (int r = 0; r < 8; ++r) {
        const float4 t = *reinterpret_cast<const float4*>(
            w_in + (size_t)(rowBase + rowHalf + r) * NN + colBase);
        w[r][0] = t.x; w[r][1] = t.y; w[r][2] = t.z; w[r][3] = t.w;
    }
    // register traces: tp for own 4 cols (warp-pair replicates, deterministic);
    // tpo replica for this warp's 8 rows in lanes 0..7
    float4 p = *reinterpret_cast<const float4*>(tpre_in + colBase);
    float  q = (lane < 8) ? tpost_in[rowBase + rowHalf + lane] : 0.0f;
    float  v = 0.0f;                               // membrane (warp W_UPD lanes<16)

    // all threads have read `base` before the updater overwrites the flag below
    __syncthreads();

    // ---- step 0: z = 0 -> i_syn = 0, no weight update ----
    if (warp == W_UPD) {
        float zn = 0.0f;
        if (lane < RPB) {
            const float x = __ldcg(&exc[rowBase + lane]);
            v = __fadd_rn(v, __fmul_rn(0.1f, __fadd_rn(__fadd_rn(-v, 0.0f), x)));
            zn = (__fsub_rn(v, 1.0f) > 0.0f) ? 1.0f : 0.0f;
            v = (zn > 0.0f) ? 0.0f : v;
        }
        const unsigned bits = __ballot_sync(FULLM, zn > 0.0f) & 0xffffu;
        if (lane == 0)
            stv64(&g_flag[bid * FSTRIDE],
                  ((base + 1ull) << 16) | (unsigned long long)bits);
        if (lane < RPB) out[rowBase + lane] = zn;
    }

    for (int i = 1; i < TT; ++i) {
        const int buf = i & 1;

        // prefetch own input current (updater; overlaps the poll + pass)
        float x = 0.0f;
        if (warp == W_UPD && lane < RPB) x = __ldcg(&exc[i * NN + rowBase + lane]);

        // ---- poller warp: wait for all 128 CTAs' step-(i-1) flags ----
        if (warp == W_POLL) {
            const unsigned long long tgt = base + (unsigned long long)i;
            unsigned long long f0, f1, f2, f3;
            do {
                f0 = ldv64(&g_flag[(lane      ) * FSTRIDE]);
                f1 = ldv64(&g_flag[(lane + 32 ) * FSTRIDE]);
                f2 = ldv64(&g_flag[(lane + 64 ) * FSTRIDE]);
                f3 = ldv64(&g_flag[(lane + 96 ) * FSTRIDE]);
            } while (__ballot_sync(FULLM,
                        ((f0 >> 16) >= tgt) & ((f1 >> 16) >= tgt) &
                        ((f2 >> 16) >= tgt) & ((f3 >> 16) >= tgt)) != FULLM);
            zb[buf][lane]      = (unsigned)(f0 & 0xffffu);
            zb[buf][lane + 32] = (unsigned)(f1 & 0xffffu);
            zb[buf][lane + 64] = (unsigned)(f2 & 0xffffu);
            zb[buf][lane + 96] = (unsigned)(f3 & 0xffffu);
        }
        asm volatile("bar.sync 2, %0;" :: "n"(NTHREADS) : "memory");  // z_{i-1} ready

        // ---- expand z bits ----
        const unsigned cw = zb[buf][colWord];
        const unsigned zw = zb[buf][bid];
        const float z0 = ((cw >> (colSh + 0)) & 1u) ? 1.0f : 0.0f;
        const float z1 = ((cw >> (colSh + 1)) & 1u) ? 1.0f : 0.0f;
        const float z2 = ((cw >> (colSh + 2)) & 1u) ? 1.0f : 0.0f;
        const float z3 = ((cw >> (colSh + 3)) & 1u) ? 1.0f : 0.0f;
        const float zo = (lane < 8)
            ? (((zw >> (rowHalf + lane)) & 1u) ? 1.0f : 0.0f) : 0.0f;

        // ---- trace updates (exact reference rounding) ----
        p.x = __fadd_rn(p.x, __fmul_rn(0.05f, __fadd_rn(-p.x, z0)));
        p.y = __fadd_rn(p.y, __fmul_rn(0.05f, __fadd_rn(-p.y, z1)));
        p.z = __fadd_rn(p.z, __fmul_rn(0.05f, __fadd_rn(-p.z, z2)));
        p.w = __fadd_rn(p.w, __fmul_rn(0.05f, __fadd_rn(-p.w, z3)));
        q   = __fadd_rn(q,   __fmul_rn(0.05f, __fadd_rn(-q,   zo)));

        // sp = rn(1e-3 * tp); b_i = rn(1e-3 * tpo_i), broadcasts front-loaded
        const float spx = __fmul_rn(1e-3f, p.x);
        const float spy = __fmul_rn(1e-3f, p.y);
        const float spz = __fmul_rn(1e-3f, p.z);
        const float spw = __fmul_rn(1e-3f, p.w);
        const float bq  = __fmul_rn(1e-3f, q);
        float nb[8];
        #pragma unroll
        for (int r = 0; r < 8; ++r) nb[r] = -__shfl_sync(FULLM, bq, r);

        // ---- fused pass over this warp's 8 rows (single batch, max ILP) ----
        // per element: t1 = zr ? sp_j : 0 (exact); d = fma(-b, z_j, t1) = rn(t1-t2);
        // w = max(rn(w+d), 0) [upper clip provably dead]; acc fmaf chain (fixed order)
        float acc[8];
        #pragma unroll
        for (int r = 0; r < 8; ++r) {
            const bool zr = (zw >> (rowHalf + r)) & 1u;
            float t1, d;
            t1 = zr ? spx : 0.0f;  d = __fmaf_rn(nb[r], z0, t1);
            w[r][0] = fmaxf(__fadd_rn(w[r][0], d), 0.0f);
            t1 = zr ? spy : 0.0f;  d = __fmaf_rn(nb[r], z1, t1);
            w[r][1] = fmaxf(__fadd_rn(w[r][1], d), 0.0f);
            t1 = zr ? spz : 0.0f;  d = __fmaf_rn(nb[r], z2, t1);
            w[r][2] = fmaxf(__fadd_rn(w[r][2], d), 0.0f);
            t1 = zr ? spw : 0.0f;  d = __fmaf_rn(nb[r], z3, t1);
            w[r][3] = fmaxf(__fadd_rn(w[r][3], d), 0.0f);

            float s = w[r][0] * z0;
            s = fmaf(w[r][1], z1, s);
            s = fmaf(w[r][2], z2, s);
            s = fmaf(w[r][3], z3, s);
            acc[r] = s;
        }

        // ---- 8-value xor tree over 32 lanes (R8-verified mapping) ----
        #pragma unroll
        for (int r = 0; r < 4; ++r) {
            float keep = (lane & 16) ? acc[r + 4] : acc[r];
            float send = (lane & 16) ? acc[r]     : acc[r + 4];
            acc[r] = keep + __shfl_xor_sync(FULLM, send, 16);
        }
        #pragma unroll
        for (int r = 0; r < 2; ++r) {
            float keep = (lane & 8) ? acc[r + 2] : acc[r];
            float send = (lane & 8) ? acc[r]     : acc[r + 2];
            acc[r] = keep + __shfl_xor_sync(FULLM, send, 8);
        }
        {
            float keep = (lane & 4) ? acc[1] : acc[0];
            float send = (lane & 4) ? acc[0] : acc[1];
            acc[0] = keep + __shfl_xor_sync(FULLM, send, 4);
        }
        acc[0] += __shfl_xor_sync(FULLM, acc[0], 2);
        acc[0] += __shfl_xor_sync(FULLM, acc[0], 1);
        {
            const int r_own = ((lane >> 4) & 1) * 4 + ((lane >> 3) & 1) * 2
                            + ((lane >> 2) & 1);
            if ((lane & 3) == 0)
                part[cb * RPB + rowHalf + r_own] = acc[0];
        }

        // ---- hand part[] to the updater; other warps roll ahead ----
        if (warp == W_UPD) {
            asm volatile("bar.sync 1, %0;" :: "n"(NTHREADS) : "memory");
            float zn = 0.0f;
            if (lane < RPB) {
                float isyn = 0.0f;
                #pragma unroll
                for (int k = 0; k < 16; ++k) isyn += part[k * RPB + lane];
                v = __fadd_rn(v, __fmul_rn(0.1f, __fadd_rn(__fadd_rn(-v, isyn), x)));
                zn = (__fsub_rn(v, 1.0f) > 0.0f) ? 1.0f : 0.0f;
                v = (zn > 0.0f) ? 0.0f : v;
            }
            // flag (the critical edge) FIRST; harness-only out[] store after
            if (i < TT - 1) {
                const unsigned bits = __ballot_sync(FULLM, zn > 0.0f) & 0xffffu;
                if (lane == 0)
                    stv64(&g_flag[bid * FSTRIDE],
                          ((base + (unsigned long long)(i + 1)) << 16) |
                          (unsigned long long)bits);
            }
            if (lane < RPB) out[(size_t)i * NN + rowBase + lane] = zn;
        } else {
            asm volatile("bar.arrive 1, %0;" :: "n"(NTHREADS) : "memory");
        }
    }
}

extern "C" void kernel_launch(void* const* d_in, const int* in_sizes, int n_in,
                              void* d_out, int out_size) {
    const float* exc   = (const float*)d_in[0];  // [T, N]
    const float* w     = (const float*)d_in[1];  // [N, N]
    const float* tpre  = (const float*)d_in[2];  // [N]
    const float* tpost = (const float*)d_in[3];  // [N]
    float*       out   = (float*)d_out;          // [T, N]

    snn_persistent<<<NCTA, NTHREADS>>>(exc, w, tpre, tpost, out);
}

// round 17
// speedup vs baseline: 1.6618x; 1.0237x over previous
#include <cuda_runtime.h>

#define TT       64
#define NN       2048
#define RPB      16                 // rows (post-neurons) per CTA
#define NCTA     (NN / RPB)         // 128 CTAs (1 per SM)
#define NTHREADS 1024
#define FULLM    0xffffffffu
#define FSTRIDE  4                  // flag padding: 4 u64 = 32B sector per CTA
#define W_UPD    31                 // updater warp (highest wid -> arbiter priority)
#define W_POLL   30                 // poller warp

// per-CTA flag: (step_count << 16) | 16-bit spike mask; 32B-padded.
// Count monotonic (48b) across graph replays.
__device__ unsigned long long g_flag[NCTA * FSTRIDE];

__device__ __forceinline__ unsigned long long ldv64(const unsigned long long* a) {
    unsigned long long r;
    asm volatile("ld.volatile.global.u64 %0, [%1];" : "=l"(r) : "l"(a) : "memory");
    return r;
}
__device__ __forceinline__ void stv64(unsigned long long* a, unsigned long long v) {
    asm volatile("st.volatile.global.u64 [%0], %1;" :: "l"(a), "l"(v) : "memory");
}

__global__ void __launch_bounds__(NTHREADS, 1)
snn_persistent(const float* __restrict__ exc,
               const float* __restrict__ w_in,
               const float* __restrict__ tpre_in,
               const float* __restrict__ tpost_in,
               float* __restrict__ out)
{
    __shared__ unsigned zb[2][NCTA];          // spike masks, double buffered
    __shared__ unsigned aflag[2];             // all-ones fast-path flag
    __shared__ float    part[16 * RPB];       // [colblock][row]

    const int tid  = threadIdx.x;
    const int warp = tid >> 5;
    const int lane = tid & 31;
    const int bid  = blockIdx.x;
    const int rowBase = bid * RPB;

    const int cb      = warp >> 1;                 // colblock 0..15
    const int rowHalf = (warp & 1) * 8;            // rows 0-7 or 8-15 of this CTA
    const int colBase = cb * 128 + lane * 4;       // this thread's 4 global cols
    const int colWord = colBase >> 4;              // CTA mask covering those cols
    const int colSh   = colBase & 15;

    const unsigned long long base = g_flag[bid * FSTRIDE] >> 16;   // launch-uniform

    // ---- prologue: this warp's 8 rows of w -> REGISTERS ----
    float w[8][4];
    #pragma unroll
    for (int r = 0; r < 8; ++r) {
        const float4 t = *reinterpret_cast<const float4*>(
            w_in + (size_t)(rowBase + rowHalf + r) * NN + colBase);
        w[r][0] = t.x; w[r][1] = t.y; w[r][2] = t.z; w[r][3] = t.w;
    }
    // register traces: tp for own 4 cols (warp-pair replicates, deterministic);
    // tpo replica for this warp's 8 rows in lanes 0..7
    float4 p = *reinterpret_cast<const float4*>(tpre_in + colBase);
    float  q = (lane < 8) ? tpost_in[rowBase + rowHalf + lane] : 0.0f;
    float  v = 0.0f;                               // membrane (warp W_UPD lanes<16)

    // all threads have read `base` before the updater overwrites the flag below
    __syncthreads();

    // ---- step 0: z = 0 -> i_syn = 0, no weight update ----
    if (warp == W_UPD) {
        float zn = 0.0f;
        if (lane < RPB) {
            const float x = __ldcg(&exc[rowBase + lane]);
            v = __fadd_rn(v, __fmul_rn(0.1f, __fadd_rn(__fadd_rn(-v, 0.0f), x)));
            zn = (__fsub_rn(v, 1.0f) > 0.0f) ? 1.0f : 0.0f;
            v = (zn > 0.0f) ? 0.0f : v;
        }
        const unsigned bits = __ballot_sync(FULLM, zn > 0.0f) & 0xffffu;
        if (lane == 0)
            stv64(&g_flag[bid * FSTRIDE],
                  ((base + 1ull) << 16) | (unsigned long long)bits);
        if (lane < RPB) out[rowBase + lane] = zn;
    }

    for (int i = 1; i < TT; ++i) {
        const int buf = i & 1;

        // prefetch own input current (updater; overlaps the poll + pass)
        float x = 0.0f;
        if (warp == W_UPD && lane < RPB) x = __ldcg(&exc[i * NN + rowBase + lane]);

        // ---- poller warp: wait for all 128 CTAs' step-(i-1) flags ----
        if (warp == W_POLL) {
            const unsigned long long tgt = base + (unsigned long long)i;
            unsigned long long f0, f1, f2, f3;
            do {
                f0 = ldv64(&g_flag[(lane      ) * FSTRIDE]);
                f1 = ldv64(&g_flag[(lane + 32 ) * FSTRIDE]);
                f2 = ldv64(&g_flag[(lane + 64 ) * FSTRIDE]);
                f3 = ldv64(&g_flag[(lane + 96 ) * FSTRIDE]);
            } while (__ballot_sync(FULLM,
                        ((f0 >> 16) >= tgt) & ((f1 >> 16) >= tgt) &
                        ((f2 >> 16) >= tgt) & ((f3 >> 16) >= tgt)) != FULLM);
            zb[buf][lane]      = (unsigned)(f0 & 0xffffu);
            zb[buf][lane + 32] = (unsigned)(f1 & 0xffffu);
            zb[buf][lane + 64] = (unsigned)(f2 & 0xffffu);
            zb[buf][lane + 96] = (unsigned)(f3 & 0xffffu);
            // all-ones fast-path detection (z saturates after ~10 steps)
            const unsigned andall = (unsigned)(f0 & f1 & f2 & f3) & 0xffffu;
            const bool all1 = __all_sync(FULLM, andall == 0xffffu);
            if (lane == 0) aflag[buf] = all1 ? 1u : 0u;
        }
        asm volatile("bar.sync 2, %0;" :: "n"(NTHREADS) : "memory");  // z_{i-1} ready

        float acc[8];

        if (aflag[buf]) {
            // ======== FAST PATH: z == all-ones (bit-exact specialization) ====
            const float zo = (lane < 8) ? 1.0f : 0.0f;
            p.x = __fadd_rn(p.x, __fmul_rn(0.05f, __fadd_rn(-p.x, 1.0f)));
            p.y = __fadd_rn(p.y, __fmul_rn(0.05f, __fadd_rn(-p.y, 1.0f)));
            p.z = __fadd_rn(p.z, __fmul_rn(0.05f, __fadd_rn(-p.z, 1.0f)));
            p.w = __fadd_rn(p.w, __fmul_rn(0.05f, __fadd_rn(-p.w, 1.0f)));
            q   = __fadd_rn(q,   __fmul_rn(0.05f, __fadd_rn(-q,   zo)));

            const float spx = __fmul_rn(1e-3f, p.x);
            const float spy = __fmul_rn(1e-3f, p.y);
            const float spz = __fmul_rn(1e-3f, p.z);
            const float spw = __fmul_rn(1e-3f, p.w);
            const float bq  = __fmul_rn(1e-3f, q);
            float nb[8];
            #pragma unroll
            for (int r = 0; r < 8; ++r) nb[r] = -__shfl_sync(FULLM, bq, r);

            // zr=1, z_j=1: d = rn(sp_j - b) via FADD(sp, nb); dot fma(w,1,s)=rn(w+s)
            #pragma unroll
            for (int r = 0; r < 8; ++r) {
                w[r][0] = fmaxf(__fadd_rn(w[r][0], __fadd_rn(spx, nb[r])), 0.0f);
                w[r][1] = fmaxf(__fadd_rn(w[r][1], __fadd_rn(spy, nb[r])), 0.0f);
                w[r][2] = fmaxf(__fadd_rn(w[r][2], __fadd_rn(spz, nb[r])), 0.0f);
                w[r][3] = fmaxf(__fadd_rn(w[r][3], __fadd_rn(spw, nb[r])), 0.0f);
                float s = w[r][0];                    // w0*1 exact
                s = __fadd_rn(s, w[r][1]);            // == fma(w1,1,s)
                s = __fadd_rn(s, w[r][2]);
                s = __fadd_rn(s, w[r][3]);
                acc[r] = s;
            }
        } else {
            // ======== GENERAL PATH (identical to the 207us kernel) ===========
            const unsigned cw = zb[buf][colWord];
            const unsigned zw = zb[buf][bid];
            const float z0 = ((cw >> (colSh + 0)) & 1u) ? 1.0f : 0.0f;
            const float z1 = ((cw >> (colSh + 1)) & 1u) ? 1.0f : 0.0f;
            const float z2 = ((cw >> (colSh + 2)) & 1u) ? 1.0f : 0.0f;
            const float z3 = ((cw >> (colSh + 3)) & 1u) ? 1.0f : 0.0f;
            const float zo = (lane < 8)
                ? (((zw >> (rowHalf + lane)) & 1u) ? 1.0f : 0.0f) : 0.0f;

            p.x = __fadd_rn(p.x, __fmul_rn(0.05f, __fadd_rn(-p.x, z0)));
            p.y = __fadd_rn(p.y, __fmul_rn(0.05f, __fadd_rn(-p.y, z1)));
            p.z = __fadd_rn(p.z, __fmul_rn(0.05f, __fadd_rn(-p.z, z2)));
            p.w = __fadd_rn(p.w, __fmul_rn(0.05f, __fadd_rn(-p.w, z3)));
            q   = __fadd_rn(q,   __fmul_rn(0.05f, __fadd_rn(-q,   zo)));

            const float spx = __fmul_rn(1e-3f, p.x);
            const float spy = __fmul_rn(1e-3f, p.y);
            const float spz = __fmul_rn(1e-3f, p.z);
            const float spw = __fmul_rn(1e-3f, p.w);
            const float bq  = __fmul_rn(1e-3f, q);
            float nb[8];
            #pragma unroll
            for (int r = 0; r < 8; ++r) nb[r] = -__shfl_sync(FULLM, bq, r);

            #pragma unroll
            for (int r = 0; r < 8; ++r) {
                const bool zr = (zw >> (rowHalf + r)) & 1u;
                float t1, d;
                t1 = zr ? spx : 0.0f;  d = __fmaf_rn(nb[r], z0, t1);
                w[r][0] = fmaxf(__fadd_rn(w[r][0], d), 0.0f);
                t1 = zr ? spy : 0.0f;  d = __fmaf_rn(nb[r], z1, t1);
                w[r][1] = fmaxf(__fadd_rn(w[r][1], d), 0.0f);
                t1 = zr ? spz : 0.0f;  d = __fmaf_rn(nb[r], z2, t1);
                w[r][2] = fmaxf(__fadd_rn(w[r][2], d), 0.0f);
                t1 = zr ? spw : 0.0f;  d = __fmaf_rn(nb[r], z3, t1);
                w[r][3] = fmaxf(__fadd_rn(w[r][3], d), 0.0f);

                float s = w[r][0] * z0;
                s = fmaf(w[r][1], z1, s);
                s = fmaf(w[r][2], z2, s);
                s = fmaf(w[r][3], z3, s);
                acc[r] = s;
            }
        }

        // ---- 8-value xor tree over 32 lanes (R8-verified mapping, shared) ----
        #pragma unroll
        for (int r = 0; r < 4; ++r) {
            float keep = (lane & 16) ? acc[r + 4] : acc[r];
            float send = (lane & 16) ? acc[r]     : acc[r + 4];
            acc[r] = keep + __shfl_xor_sync(FULLM, send, 16);
        }
        #pragma unroll
        for (int r = 0; r < 2; ++r) {
            float keep = (lane & 8) ? acc[r + 2] : acc[r];
            float send = (lane & 8) ? acc[r]     : acc[r + 2];
            acc[r] = keep + __shfl_xor_sync(FULLM, send, 8);
        }
        {
            float keep = (lane & 4) ? acc[1] : acc[0];
            float send = (lane & 4) ? acc[0] : acc[1];
            acc[0] = keep + __shfl_xor_sync(FULLM, send, 4);
        }
        acc[0] += __shfl_xor_sync(FULLM, acc[0], 2);
        acc[0] += __shfl_xor_sync(FULLM, acc[0], 1);
        {
            const int r_own = ((lane >> 4) & 1) * 4 + ((lane >> 3) & 1) * 2
                            + ((lane >> 2) & 1);
            if ((lane & 3) == 0)
                part[cb * RPB + rowHalf + r_own] = acc[0];
        }

        // ---- hand part[] to the updater; other warps roll ahead ----
        if (warp == W_UPD) {
            asm volatile("bar.sync 1, %0;" :: "n"(NTHREADS) : "memory");
            float zn = 0.0f;
            if (lane < RPB) {
                float isyn = 0.0f;
                #pragma unroll
                for (int k = 0; k < 16; ++k) isyn += part[k * RPB + lane];
                v = __fadd_rn(v, __fmul_rn(0.1f, __fadd_rn(__fadd_rn(-v, isyn), x)));
                zn = (__fsub_rn(v, 1.0f) > 0.0f) ? 1.0f : 0.0f;
                v = (zn > 0.0f) ? 0.0f : v;
            }
            // flag (the critical edge) FIRST; harness-only out[] store after
            if (i < TT - 1) {
                const unsigned bits = __ballot_sync(FULLM, zn > 0.0f) & 0xffffu;
                if (lane == 0)
                    stv64(&g_flag[bid * FSTRIDE],
                          ((base + (unsigned long long)(i + 1)) << 16) |
                          (unsigned long long)bits);
            }
            if (lane < RPB) out[(size_t)i * NN + rowBase + lane] = zn;
        } else {
            asm volatile("bar.arrive 1, %0;" :: "n"(NTHREADS) : "memory");
        }
    }
}

extern "C" void kernel_launch(void* const* d_in, const int* in_sizes, int n_in,
                              void* d_out, int out_size) {
    const float* exc   = (const float*)d_in[0];  // [T, N]
    const float* w     = (const float*)d_in[1];  // [N, N]
    const float* tpre  = (const float*)d_in[2];  // [N]
    const float* tpost = (const float*)d_in[3];  // [N]
    float*       out   = (float*)d_out;          // [T, N]

    snn_persistent<<<NCTA, NTHREADS>>>(exc, w, tpre, tpost, out);
}